// round 8
// baseline (speedup 1.0000x reference)
#include <cuda_runtime.h>
#include <math.h>

#define BATCH 2048
#define NC    9605
#define NL    8
#define MAXWL 512
#define NTHR  256
#define CAP   2048    // candidate cap (shares smem with fallback histogram)

__device__ int           g_wl_count;   // 0-init; reset by last block each launch
__device__ int           g_wl_idx[MAXWL];
__device__ unsigned char g_wl_mask[MAXWL];
__device__ float         g_row_val[BATCH];
__device__ int           g_done;       // 0-init; reset each launch
__device__ int           g_wl_ready;   // 0-init; reset each launch

__device__ __forceinline__ float sigmoidf_(float v) {
    return 1.0f / (1.0f + expf(-v));   // v = -1e30 -> 0 (correct)
}
__device__ __forceinline__ unsigned f2k(unsigned u) {          // monotone float->uint
    return (u & 0x80000000u) ? ~u : (u | 0x80000000u);
}
__device__ __forceinline__ float k2f(unsigned k) {
    return (k & 0x80000000u) ? __uint_as_float(k ^ 0x80000000u)
                             : __uint_as_float(~k);
}

// block max with smem bounce (reusable across rounds: trailing sync)
__device__ __forceinline__ float block_max_f(float v, float* sw, int tid) {
#pragma unroll
    for (int s = 16; s > 0; s >>= 1)
        v = fmaxf(v, __shfl_xor_sync(0xffffffffu, v, s));
    if ((tid & 31) == 0) sw[tid >> 5] = v;
    __syncthreads();
    float m = sw[0];
#pragma unroll
    for (int w = 1; w < NTHR / 32; ++w) m = fmaxf(m, sw[w]);
    __syncthreads();
    return m;
}

// pick8: suffix-select over 2048 bins (thread t owns bins [8t,8t+8)).
__device__ __forceinline__ void pick8(const unsigned* __restrict__ hist,
                                      unsigned* __restrict__ wsum,
                                      unsigned* __restrict__ sb,
                                      unsigned* __restrict__ sw,
                                      unsigned* __restrict__ sc,
                                      unsigned want, int tid) {
    unsigned v[8];
    unsigned tot = 0;
#pragma unroll
    for (int i = 0; i < 8; ++i) { v[i] = hist[tid * 8 + i]; tot += v[i]; }
    unsigned incl = tot;
#pragma unroll
    for (int d = 1; d < 32; d <<= 1) {
        unsigned n = __shfl_down_sync(0xffffffffu, incl, d);
        if ((tid & 31) + d < 32) incl += n;
    }
    if ((tid & 31) == 0) wsum[tid >> 5] = incl;
    __syncthreads();
    unsigned above = incl - tot;
#pragma unroll
    for (int w = 0; w < NTHR / 32; ++w)
        if (w > (tid >> 5)) above += wsum[w];
    unsigned suf = above;
#pragma unroll
    for (int j = 7; j >= 0; --j) {
        unsigned nsuf = suf + v[j];
        if (suf < want && want <= nsuf) {
            *sb = (unsigned)(tid * 8 + j); *sw = want - suf; *sc = v[j];
        }
        suf = nsuf;
    }
    __syncthreads();
}

// pick1: suffix-select over <=256 bins (thread t owns bin t).
__device__ __forceinline__ void pick1(const unsigned* __restrict__ hist, int nbins,
                                      unsigned* __restrict__ wsum,
                                      unsigned* __restrict__ sb,
                                      unsigned* __restrict__ sw,
                                      unsigned* __restrict__ sc,
                                      unsigned want, int tid) {
    unsigned v = (tid < nbins) ? hist[tid] : 0u;
    unsigned incl = v;
#pragma unroll
    for (int d = 1; d < 32; d <<= 1) {
        unsigned n = __shfl_down_sync(0xffffffffu, incl, d);
        if ((tid & 31) + d < 32) incl += n;
    }
    if ((tid & 31) == 0) wsum[tid >> 5] = incl;
    __syncthreads();
    unsigned above = incl - v;
#pragma unroll
    for (int w = 0; w < NTHR / 32; ++w)
        if (w > (tid >> 5)) above += wsum[w];
    if (above < want && want <= above + v) { *sb = (unsigned)tid; *sw = want - above; *sc = v; }
    __syncthreads();
}

// ---------------------------------------------------------------------------
// Single kernel: block 0 first builds the compacted whitelist (dtype-sniffed)
// and releases g_wl_ready; every block streams its row once with float4 loads,
// filtering candidates > sampled pivot; exact rank-select among candidates
// (histogram fallback for pathological inputs); whitelist maxes / pos bits /
// union max; epilogue; last block computes the mean and resets state.
// ---------------------------------------------------------------------------
__global__ void __launch_bounds__(NTHR, 6)
row_kernel(const float* __restrict__ x, const float* __restrict__ y,
           const void* __restrict__ wlraw, float* __restrict__ out) {
    __shared__ unsigned s_hist[CAP];              // candidates OR fallback hist
    __shared__ unsigned s_wsum[NTHR / 32];
    __shared__ float    s_fw[NTHR / 32];
    __shared__ unsigned s_bin, s_want, s_cnt;
    __shared__ unsigned s_ncand, s_sel;
    __shared__ int      s_fl[4];
    __shared__ unsigned s_lmaxk[NTHR / 32][NL];
    __shared__ unsigned s_unk[NTHR / 32];
    __shared__ unsigned s_pb[NTHR / 32];
    __shared__ int      s_last;

    const int b   = blockIdx.x;
    const int tid = threadIdx.x;
    const float* xr = x + (size_t)b * NC;
    const float* yr = y + (size_t)b * NC;

    // ================= block 0: build whitelist, then release ==============
    if (b == 0) {
        if (tid < 4) s_fl[tid] = 0;
        __syncthreads();
        const int NQ = (NL * NC) / 4;
        const int*   ip = (const int*)wlraw;
        const float* fp = (const float*)wlraw;
        for (int i = tid; i < NQ; i += NTHR) {
            int v = ip[i];
            float f = fp[i];
            if (v != 0 && v != 1)          s_fl[0] = 1;
            if (!(f == 0.0f || f == 1.0f)) s_fl[2] = 1;
            if (f == 1.0f)                 s_fl[3] = 1;
        }
        __syncthreads();
        const int mode = (!s_fl[2] && s_fl[3]) ? 2 : (!s_fl[0] ? 1 : 0);  // f32/i32/u8
        const unsigned char* up = (const unsigned char*)wlraw;
        for (int c = tid; c < NC; c += NTHR) {
            unsigned m = 0;
#pragma unroll
            for (int l = 0; l < NL; ++l) {
                bool on;
                if      (mode == 2) on = (fp[l * NC + c] != 0.0f);
                else if (mode == 1) on = (ip[l * NC + c] != 0);
                else                on = (up[l * NC + c] != 0);
                if (on) m |= (1u << l);
            }
            if (m) {
                int p = atomicAdd(&g_wl_count, 1);
                g_wl_idx[p]  = c;
                g_wl_mask[p] = (unsigned char)m;
            }
        }
        __syncthreads();
        if (tid == 0) { __threadfence(); atomicExch(&g_wl_ready, 1); }
    }

    // ================= pivot from 256 strided samples ======================
    float pv = __ldg(xr + tid * 37);              // 37*255 = 9435 < NC
    float pivot = pv;
#pragma unroll
    for (int r = 0; r < 4; ++r) {
        pivot = block_max_f(pv, s_fw, tid);
        if (r < 3 && pv == pivot) pv = -INFINITY; // drop ties -> 4th distinct
    }

    // ================= fused stream: float4 + candidate filter ============
    if (tid == 0) s_ncand = 0;
    __syncthreads();

    const int a    = (-b) & 3;                    // peel to 16B alignment
    const int n4   = (NC - a) >> 2;
    const int tcnt = (NC - a) & 3;
    const float4* xr4 = (const float4*)(xr + a);

    if (tid < a) {                                // head peel (<=3)
        float v = __ldg(xr + tid);
        if (v > pivot) {
            unsigned p = atomicAdd(&s_ncand, 1u);
            if (p < CAP) s_hist[p] = f2k(__float_as_uint(v));
        }
    }
    if (tid < tcnt) {                             // tail peel (<=3)
        float v = __ldg(xr + a + 4 * n4 + tid);
        if (v > pivot) {
            unsigned p = atomicAdd(&s_ncand, 1u);
            if (p < CAP) s_hist[p] = f2k(__float_as_uint(v));
        }
    }
    for (int base = 0; base < n4; base += NTHR * 4) {
        float4 q[4];
        bool   vb[4];
#pragma unroll
        for (int u = 0; u < 4; ++u) {
            const int j = base + u * NTHR + tid;
            vb[u] = (j < n4);
            if (vb[u]) q[u] = __ldg(xr4 + j);
        }
#pragma unroll
        for (int u = 0; u < 4; ++u) {
            if (!vb[u]) continue;
            const float vv[4] = {q[u].x, q[u].y, q[u].z, q[u].w};
#pragma unroll
            for (int e = 0; e < 4; ++e) {
                if (vv[e] > pivot) {
                    unsigned p = atomicAdd(&s_ncand, 1u);
                    if (p < CAP) s_hist[p] = f2k(__float_as_uint(vv[e]));
                }
            }
        }
    }
    __syncthreads();

    // ================= exact 11th-largest ==================================
    unsigned key11;
    const unsigned nc0 = s_ncand;
    if (nc0 >= 11u && nc0 <= CAP) {
        // rank-select among candidates (all strictly > pivot -> contains top-11)
        const int n = (int)nc0;
        for (int i = tid; i < n; i += NTHR) {
            const unsigned kk = s_hist[i];
            unsigned gt = 0, ge = 0;
            for (int j = 0; j < n; ++j) {
                const unsigned u = s_hist[j];
                gt += (u > kk);
                ge += (u >= kk);
            }
            if (gt < 11u && 11u <= ge) s_sel = kk;
        }
        __syncthreads();
        key11 = s_sel;
    } else {
        // ---------- fallback: exact histogram select (rare/adversarial) ----
        __syncthreads();
#pragma unroll
        for (int i = 0; i < CAP / NTHR; ++i) s_hist[tid + i * NTHR] = 0;
        __syncthreads();
        for (int c = tid; c < NC; c += NTHR) {
            const unsigned key = f2k(__float_as_uint(__ldg(xr + c)));
            atomicAdd(&s_hist[key >> 21], 1u);
        }
        __syncthreads();
        unsigned want = 11;
        pick8(s_hist, s_wsum, &s_bin, &s_want, &s_cnt, want, tid);
        unsigned prefix = s_bin;
        int      pbits  = 11;
        unsigned cnt    = s_cnt;
        want = s_want;
        __syncthreads();
        while (cnt > CAP && pbits < 32) {
            const int nb = (32 - pbits < 8) ? (32 - pbits) : 8;
            if (tid < (1 << nb)) s_hist[tid] = 0;
            __syncthreads();
            for (int c = tid; c < NC; c += NTHR) {
                const unsigned key = f2k(__float_as_uint(__ldg(xr + c)));
                if ((key >> (32 - pbits)) == prefix)
                    atomicAdd(&s_hist[(key >> (32 - pbits - nb)) & ((1u << nb) - 1u)], 1u);
            }
            __syncthreads();
            pick1(s_hist, 1 << nb, s_wsum, &s_bin, &s_want, &s_cnt, want, tid);
            prefix = (prefix << nb) | s_bin;
            pbits += nb;
            cnt  = s_cnt;
            want = s_want;
            __syncthreads();
        }
        if (pbits >= 32) {
            key11 = prefix;
        } else {
            if (tid == 0) s_ncand = 0;
            __syncthreads();
            for (int c = tid; c < NC; c += NTHR) {
                const unsigned key = f2k(__float_as_uint(__ldg(xr + c)));
                if ((key >> (32 - pbits)) == prefix) {
                    unsigned p = atomicAdd(&s_ncand, 1u);
                    if (p < CAP) s_hist[p] = key;
                }
            }
            __syncthreads();
            const int n = (int)s_ncand;
            for (int i = tid; i < n; i += NTHR) {
                const unsigned kk = s_hist[i];
                unsigned gt = 0, ge = 0;
                for (int j = 0; j < n; ++j) {
                    const unsigned u = s_hist[j];
                    gt += (u > kk);
                    ge += (u >= kk);
                }
                if (gt < want && want <= ge) s_sel = kk;
            }
            __syncthreads();
            key11 = s_sel;
        }
    }

    // ================= wait for whitelist (long since ready) ===============
    if (tid == 0 && b != 0) {
        while (atomicOr(&g_wl_ready, 0) == 0) __nanosleep(64);
        __threadfence();
    }
    __syncthreads();

    // ================= whitelist gather (x from L2, y sparse) ==============
    const unsigned KNEG = f2k(__float_as_uint(-1e30f));
    const int nwl = g_wl_count;
    unsigned lmaxk[NL];
#pragma unroll
    for (int l = 0; l < NL; ++l) lmaxk[l] = KNEG;
    unsigned unk = KNEG, pos = 0;

    for (int e = tid; e < nwl; e += NTHR) {
        const int      c  = g_wl_idx[e];
        const unsigned m  = g_wl_mask[e];
        const unsigned kv = f2k(__float_as_uint(__ldg(xr + c)));
        const float    yv = __ldg(yr + c);
        unk = max(unk, kv);
        if (yv > 0.0f) pos |= m;
#pragma unroll
        for (int l = 0; l < NL; ++l)
            if (m & (1u << l)) lmaxk[l] = max(lmaxk[l], kv);
    }
#pragma unroll
    for (int s = 16; s > 0; s >>= 1) {
#pragma unroll
        for (int l = 0; l < NL; ++l)
            lmaxk[l] = max(lmaxk[l], __shfl_xor_sync(0xffffffffu, lmaxk[l], s));
        unk = max(unk, __shfl_xor_sync(0xffffffffu, unk, s));
        pos |= __shfl_xor_sync(0xffffffffu, pos, s);
    }
    const int warp = tid >> 5, lane = tid & 31;
    if (lane == 0) {
#pragma unroll
        for (int l = 0; l < NL; ++l) s_lmaxk[warp][l] = lmaxk[l];
        s_unk[warp] = unk;
        s_pb[warp]  = pos;
    }
    __syncthreads();

    if (tid == 0) {
#pragma unroll
        for (int w = 1; w < NTHR / 32; ++w) {
#pragma unroll
            for (int l = 0; l < NL; ++l) lmaxk[l] = max(lmaxk[l], s_lmaxk[w][l]);
            unk = max(unk, s_unk[w]);
            pos |= s_pb[w];
        }

        const float thres = fmaxf(sigmoidf_(k2f(key11)), 0.5f);   // ALPHA_OTHER

        unsigned ck = KNEG, ik = KNEG;
#pragma unroll
        for (int l = 0; l < NL; ++l) {
            if (pos & (1u << l)) ck = max(ck, lmaxk[l]);
            else                 ik = max(ik, lmaxk[l]);
        }

        float x1, x2, coef;
        if (pos) {                                   // any_correct
            x1   = sigmoidf_(k2f(ck));
            x2   = fmaxf(sigmoidf_(k2f(ik)), thres); // covers any_incorrect branch
            coef = 1.0f;
        } else {
            x1   = thres;
            x2   = sigmoidf_(k2f(unk));
            coef = 0.5f;                             // 1 - ALPHA
        }
        const float d    = x2 - x1 + 0.1f;           // ALPHA1
        const float rank = (d > 0.0f ? 2.0f : 1.0f) * sigmoidf_(10.0f * d);

        g_row_val[b] = coef * rank;
        __threadfence();
        const int t = atomicAdd(&g_done, 1);
        s_last = (t == BATCH - 1);
    }
    __syncthreads();

    // ================= last block: mean + state reset ======================
    if (s_last) {
        float* s_red = (float*)s_hist;
        float acc = 0.0f;
        for (int i = tid; i < BATCH; i += NTHR) acc += g_row_val[i];
        s_red[tid] = acc;
        __syncthreads();
        for (int off = NTHR / 2; off > 0; off >>= 1) {
            if (tid < off) s_red[tid] += s_red[tid + off];
            __syncthreads();
        }
        if (tid == 0) {
            out[0]     = s_red[0] * (1.0f / (float)BATCH);
            g_done     = 0;
            g_wl_count = 0;
            g_wl_ready = 0;
        }
    }
}

extern "C" void kernel_launch(void* const* d_in, const int* in_sizes, int n_in,
                              void* d_out, int out_size) {
    const float* x  = (const float*)d_in[0];
    const float* y  = (const float*)d_in[1];
    // d_in[2] = y_neg: never affects the result, never read.
    const void*  wl = d_in[3];

    row_kernel<<<BATCH, NTHR>>>(x, y, wl, (float*)d_out);
}